// round 6
// baseline (speedup 1.0000x reference)
#include <cuda_runtime.h>
#include <cuda_bf16.h>
#include <cuda_fp16.h>
#include <cstdint>

// ---------------------------------------------------------------------------
// Problem constants
#define N_ROWS   32768          // B*H*W*L = 8*16*16*16
#define K_CODES  1024
#define D_DIM    256
#define S_SZ     4096
#define QUANT_ELEMS 8388608     // 8*256*4096

// GEMM tiling: CTA 128x128, 4 warps, warp tile 64x64
#define BM 128
#define BKN 128
#define KC 64                   // bf16 k-chunk (128 bytes/row)

// smem layout (dynamic): A0 | B0 | A1 | B1 | bnorm
#define TILE_BYTES 16384        // 128 rows x 128B
#define SM_BNORM   65536
#define SM_TOTAL   66048

// ---------------------------------------------------------------------------
// Scratch (__device__ globals; no runtime allocation)
__device__ __nv_bfloat16 g_zbf[N_ROWS * D_DIM];      // z transposed (n,d) bf16
__device__ float  g_zt[N_ROWS * D_DIM];              // z transposed (n,d) fp32 (exact)
__device__ __nv_bfloat16 g_cbbf[K_CODES * D_DIM];    // codebook bf16
__device__ __half g_scores_h[N_ROWS * K_CODES];      // approx scores fp16 (64 MB)
__device__ float  g_a[N_ROWS];                       // ||z_n||^2 (sequential-d fmaf!)
__device__ float  g_sabs[N_ROWS];                    // sum_d |z_nd|
__device__ float  g_b[K_CODES];                      // ||e_k||^2
__device__ unsigned long long g_best[N_ROWS];        // packed approx min (fp32 key)
__device__ int    g_idx[N_ROWS];                     // final indices
__device__ double g_part[8192];                      // loss partials

// ---------------------------------------------------------------------------
__device__ __forceinline__ uint32_t smem_u32(const void* p) {
    uint32_t a;
    asm("{ .reg .u64 t; cvta.to.shared.u64 t, %1; cvt.u32.u64 %0, t; }" : "=r"(a) : "l"(p));
    return a;
}
#define SW128(o) ((o) ^ (((o) >> 3) & 0x70))

__device__ __forceinline__ void cp16(uint32_t saddr, const void* gaddr) {
    asm volatile("cp.async.cg.shared.global [%0], [%1], 16;" :: "r"(saddr), "l"(gaddr));
}
#define CP_COMMIT() asm volatile("cp.async.commit_group;")
#define CP_WAIT(n)  asm volatile("cp.async.wait_group %0;" :: "n"(n))

__device__ __forceinline__ void ldsm_x4(uint32_t* r, uint32_t saddr) {
    asm volatile("ldmatrix.sync.aligned.m8n8.x4.shared.b16 {%0,%1,%2,%3}, [%4];"
                 : "=r"(r[0]), "=r"(r[1]), "=r"(r[2]), "=r"(r[3]) : "r"(saddr));
}
__device__ __forceinline__ void mma_bf16(float* c, const uint32_t* a, uint32_t b0, uint32_t b1) {
    asm volatile("mma.sync.aligned.m16n8k16.row.col.f32.bf16.bf16.f32 "
                 "{%0,%1,%2,%3}, {%4,%5,%6,%7}, {%8,%9}, {%0,%1,%2,%3};"
                 : "+f"(c[0]), "+f"(c[1]), "+f"(c[2]), "+f"(c[3])
                 : "r"(a[0]), "r"(a[1]), "r"(a[2]), "r"(a[3]), "r"(b0), "r"(b1));
}

// pack two floats -> one u32 of bf16x2 (round-to-nearest)
__device__ __forceinline__ uint32_t pack_bf16x2(float lo, float hi) {
    __nv_bfloat162 t = __floats2bfloat162_rn(lo, hi);
    uint32_t u;
    memcpy(&u, &t, 4);
    return u;
}

// monotonic float->uint key (handles negatives)
__device__ __forceinline__ uint32_t fkey(float s) {
    uint32_t u = __float_as_uint(s);
    return (u & 0x80000000u) ? ~u : (u | 0x80000000u);
}
__device__ __forceinline__ float funkey(uint32_t k) {
    return (k & 0x80000000u) ? __uint_as_float(k ^ 0x80000000u) : __uint_as_float(~k);
}

// ---------------------------------------------------------------------------
// 1) Codebook: bf16 convert + ||e_k||^2, warp per row (1024 warps).
__global__ void prep_cbnorm_kernel(const float* __restrict__ cb) {
    int w = blockIdx.x * 8 + (threadIdx.x >> 5);   // row 0..1023
    int lane = threadIdx.x & 31;
    const float* p = cb + (size_t)w * D_DIM + lane * 8;
    float4 v0 = *(const float4*)p;
    float4 v1 = *(const float4*)(p + 4);
    uint4 packed;
    packed.x = pack_bf16x2(v0.x, v0.y);
    packed.y = pack_bf16x2(v0.z, v0.w);
    packed.z = pack_bf16x2(v1.x, v1.y);
    packed.w = pack_bf16x2(v1.z, v1.w);
    *(uint4*)(g_cbbf + (size_t)w * D_DIM + lane * 8) = packed;
    float acc = 0.0f;
    acc = fmaf(v0.x, v0.x, acc); acc = fmaf(v0.y, v0.y, acc);
    acc = fmaf(v0.z, v0.z, acc); acc = fmaf(v0.w, v0.w, acc);
    acc = fmaf(v1.x, v1.x, acc); acc = fmaf(v1.y, v1.y, acc);
    acc = fmaf(v1.z, v1.z, acc); acc = fmaf(v1.w, v1.w, acc);
    #pragma unroll
    for (int off = 16; off > 0; off >>= 1)
        acc += __shfl_xor_sync(0xffffffffu, acc, off);
    if (lane == 0) g_b[w] = acc;
}

// 2) Transpose + convert z: (b,d,s) fp32 -> (n,d) bf16 AND (n,d) fp32
__global__ void prep_z_kernel(const float* __restrict__ z) {
    __shared__ float tile[32][33];
    int x = threadIdx.x, y = threadIdx.y;           // block (32, 8)
    int s0 = blockIdx.x * 32;
    int d0 = blockIdx.y * 32;
    int b  = blockIdx.z;
    const float* zb = z + (size_t)b * (D_DIM * S_SZ);
    #pragma unroll
    for (int i = 0; i < 4; i++)
        tile[y + 8 * i][x] = zb[(size_t)(d0 + y + 8 * i) * S_SZ + s0 + x];
    __syncthreads();
    #pragma unroll
    for (int i = 0; i < 4; i++) {
        int n = b * S_SZ + s0 + y + 8 * i;
        float v = tile[x][y + 8 * i];
        g_zt[(size_t)n * D_DIM + d0 + x]  = v;
        g_zbf[(size_t)n * D_DIM + d0 + x] = __float2bfloat16(v);
    }
}

// 3) row norms (SEQUENTIAL-d fmaf — a is ulp-sensitive in fl(a+b)) + abs sums
//    + init g_best.
__global__ void row_norms_kernel(const float* __restrict__ z) {
    int n = blockIdx.x * blockDim.x + threadIdx.x;
    int b = n >> 12, s = n & 4095;
    const float* p = z + (size_t)b * (D_DIM * S_SZ) + s;
    float acc = 0.0f, sab = 0.0f;
    #pragma unroll 8
    for (int d = 0; d < D_DIM; d++) {
        float v = p[(size_t)d * S_SZ];
        acc = fmaf(v, v, acc);
        sab += fabsf(v);
    }
    g_a[n] = acc;
    g_sabs[n] = sab;
    g_best[n] = ~0ULL;
}

// ---------------------------------------------------------------------------
// 4) HMMA bf16 GEMM: CTA 128x128, 4 warps, warp tile 64x64.
//    Per k-step: 8 ldsm.x4 feed 32 HMMA (0.25 ldsm/HMMA vs 0.375 before).
__global__ void __launch_bounds__(128, 2)
mma_kernel() {
    extern __shared__ char smem[];
    uint32_t sb = smem_u32(smem);
    int tid  = threadIdx.x;
    int wid  = tid >> 5, lane = tid & 31;
    int wm   = wid & 1;              // 0..1  (64-row slice)
    int wn   = wid >> 1;             // 0..1  (64-col slice)
    int n0   = blockIdx.x * BM;
    int k0   = blockIdx.y * BKN;

    float* bsh = (float*)(smem + SM_BNORM);
    if (tid < BKN) bsh[tid] = g_b[k0 + tid];

    // loader: 128 threads, 1 row each, 8 segs of 16B for A and B
    auto load_chunk = [&](int buf, int c) {
        uint32_t abase = sb + buf * 32768;
        uint32_t bbase = abase + TILE_BYTES;
        const __nv_bfloat16* ag = g_zbf  + (size_t)(n0 + tid) * D_DIM + c * KC;
        const __nv_bfloat16* bg = g_cbbf + (size_t)(k0 + tid) * D_DIM + c * KC;
        #pragma unroll
        for (int seg = 0; seg < 8; seg++) {
            uint32_t soff = SW128(tid * 128 + seg * 16);
            cp16(abase + soff, ag + seg * 8);
            cp16(bbase + soff, bg + seg * 8);
        }
    };

    float C[4][8][4];
    #pragma unroll
    for (int mf = 0; mf < 4; mf++)
        #pragma unroll
        for (int nf = 0; nf < 8; nf++)
            #pragma unroll
            for (int q = 0; q < 4; q++) C[mf][nf][q] = 0.0f;

    load_chunk(0, 0);
    CP_COMMIT();

    int lr = lane & 15;
    int lh = lane >> 4;

    for (int c = 0; c < 4; c++) {
        if (c < 3) { load_chunk((c + 1) & 1, c + 1); CP_COMMIT(); }
        if (c < 3) { CP_WAIT(1); } else { CP_WAIT(0); }
        __syncthreads();

        uint32_t abase = sb + (c & 1) * 32768;
        uint32_t bbase = abase + TILE_BYTES;

        #pragma unroll
        for (int ks = 0; ks < 4; ks++) {
            uint32_t a[4][4], bq[4][4];
            #pragma unroll
            for (int mf = 0; mf < 4; mf++) {
                int r = wm * 64 + mf * 16 + lr;
                ldsm_x4(a[mf], abase + SW128(r * 128 + (2 * ks + lh) * 16));
            }
            #pragma unroll
            for (int nf2 = 0; nf2 < 4; nf2++) {
                int r = wn * 64 + nf2 * 16 + lr;
                ldsm_x4(bq[nf2], bbase + SW128(r * 128 + (2 * ks + lh) * 16));
            }
            #pragma unroll
            for (int mf = 0; mf < 4; mf++)
                #pragma unroll
                for (int nf2 = 0; nf2 < 4; nf2++) {
                    mma_bf16(C[mf][2 * nf2],     a[mf], bq[nf2][0], bq[nf2][2]);
                    mma_bf16(C[mf][2 * nf2 + 1], a[mf], bq[nf2][1], bq[nf2][3]);
                }
        }
        __syncthreads();
    }

    // Epilogue: fp16 score stores + packed per-row argmin (fp32 keys)
    unsigned long long best[4][2];
    #pragma unroll
    for (int mf = 0; mf < 4; mf++) { best[mf][0] = ~0ULL; best[mf][1] = ~0ULL; }
    int gq = lane >> 2;
    int qc = (lane & 3) * 2;
    #pragma unroll
    for (int mf = 0; mf < 4; mf++) {
        int r0 = n0 + wm * 64 + mf * 16 + gq;
        #pragma unroll
        for (int nf = 0; nf < 8; nf++) {
            int colL = wn * 64 + nf * 8 + qc;
            int kk = k0 + colL;
            float b0v = bsh[colL], b1v = bsh[colL + 1];
            float s00 = b0v - 2.0f * C[mf][nf][0];
            float s01 = b1v - 2.0f * C[mf][nf][1];
            float s10 = b0v - 2.0f * C[mf][nf][2];
            float s11 = b1v - 2.0f * C[mf][nf][3];
            *(__half2*)(g_scores_h + (size_t)r0 * K_CODES + kk) =
                __floats2half2_rn(s00, s01);
            *(__half2*)(g_scores_h + (size_t)(r0 + 8) * K_CODES + kk) =
                __floats2half2_rn(s10, s11);
            unsigned long long p;
            p = ((unsigned long long)fkey(s00) << 32) | (unsigned)kk;
            best[mf][0] = min(best[mf][0], p);
            p = ((unsigned long long)fkey(s01) << 32) | (unsigned)(kk + 1);
            best[mf][0] = min(best[mf][0], p);
            p = ((unsigned long long)fkey(s10) << 32) | (unsigned)kk;
            best[mf][1] = min(best[mf][1], p);
            p = ((unsigned long long)fkey(s11) << 32) | (unsigned)(kk + 1);
            best[mf][1] = min(best[mf][1], p);
        }
    }
    #pragma unroll
    for (int mf = 0; mf < 4; mf++)
        #pragma unroll
        for (int h = 0; h < 2; h++) {
            unsigned long long v = best[mf][h];
            v = min(v, __shfl_xor_sync(0xffffffffu, v, 1));
            v = min(v, __shfl_xor_sync(0xffffffffu, v, 2));
            if ((lane & 3) == 0) {
                int row = n0 + wm * 64 + mf * 16 + h * 8 + gq;
                atomicMin(&g_best[row], v);
            }
        }
}

// ---------------------------------------------------------------------------
// 5) Candidate selection + exact fp32 rescore. Warp per row.
__global__ void __launch_bounds__(256)
select_kernel(const float* __restrict__ cb, float* __restrict__ out_idx) {
    int w = threadIdx.x >> 5, lane = threadIdx.x & 31;
    int n = blockIdx.x * 8 + w;

    // zrow in registers: lane owns d in [8*lane, 8*lane+8)
    const float* zp = g_zt + (size_t)n * D_DIM + lane * 8;
    float4 z0 = *(const float4*)zp;
    float4 z1 = *(const float4*)(zp + 4);

    unsigned long long gb64 = g_best[n];
    float smin = funkey((uint32_t)(gb64 >> 32));
    // margin: 2x bf16 GEMM err (7.6e-6*sabs each) + 2x fp16 storage RN err + slack
    float thresh = smin + g_sabs[n] * 1.6e-5f + 6.0e-4f;
    float a = g_a[n];

    const __half* sr = g_scores_h + (size_t)n * K_CODES;
    unsigned long long best = ~0ULL;
    #pragma unroll 4
    for (int j = 0; j < 32; j++) {
        float sv = __half2float(sr[lane + 32 * j]);
        unsigned mask = __ballot_sync(0xffffffffu, sv <= thresh);
        while (mask) {
            int src = __ffs(mask) - 1;
            mask &= mask - 1;
            int kc = 32 * j + src;
            const float* e = cb + (size_t)kc * D_DIM + lane * 8;
            float4 e0 = *(const float4*)e;
            float4 e1 = *(const float4*)(e + 4);
            float acc = 0.0f;
            acc = fmaf(z0.x, e0.x, acc); acc = fmaf(z0.y, e0.y, acc);
            acc = fmaf(z0.z, e0.z, acc); acc = fmaf(z0.w, e0.w, acc);
            acc = fmaf(z1.x, e1.x, acc); acc = fmaf(z1.y, e1.y, acc);
            acc = fmaf(z1.z, e1.z, acc); acc = fmaf(z1.w, e1.w, acc);
            #pragma unroll
            for (int off = 16; off > 0; off >>= 1)
                acc += __shfl_xor_sync(0xffffffffu, acc, off);
            float tsum = a + g_b[kc];                // fl(a + b)
            float dv = tsum - 2.0f * acc;            // fl(t - 2c)
            unsigned long long p =
                ((unsigned long long)__float_as_uint(dv) << 32) | (unsigned)kc;
            best = min(best, p);
        }
    }
    if (lane == 0) {
        int kk = (int)(unsigned)(best & 0xFFFFFFFFULL);
        g_idx[n] = kk;
        out_idx[n] = (float)kk;
    }
}

// ---------------------------------------------------------------------------
// 6) Gather + straight-through + loss partials
__global__ void gather_loss_kernel(const float* __restrict__ z,
                                   const float* __restrict__ cb,
                                   float* __restrict__ out_q) {
    int gid4 = blockIdx.x * blockDim.x + threadIdx.x;
    int base = gid4 * 4;
    int s = base & 4095;
    int r = base >> 12;
    int d = r & 255;
    int b = r >> 8;
    int n = b * S_SZ + s;
    float4 zv = *(const float4*)(z + base);
    float4 ov;
    int k0 = g_idx[n], k1 = g_idx[n + 1], k2 = g_idx[n + 2], k3 = g_idx[n + 3];
    float q0 = cb[(size_t)k0 * D_DIM + d];
    float q1 = cb[(size_t)k1 * D_DIM + d];
    float q2 = cb[(size_t)k2 * D_DIM + d];
    float q3 = cb[(size_t)k3 * D_DIM + d];
    float d0 = q0 - zv.x, d1 = q1 - zv.y, d2 = q2 - zv.z, d3 = q3 - zv.w;
    ov.x = zv.x + d0; ov.y = zv.y + d1; ov.z = zv.z + d2; ov.w = zv.w + d3;
    *(float4*)(out_q + base) = ov;
    float part = fmaf(d0, d0, fmaf(d1, d1, fmaf(d2, d2, d3 * d3)));
    #pragma unroll
    for (int off = 16; off > 0; off >>= 1)
        part += __shfl_down_sync(0xffffffffu, part, off);
    __shared__ float ws[8];
    int lane = threadIdx.x & 31, w = threadIdx.x >> 5;
    if (lane == 0) ws[w] = part;
    __syncthreads();
    if (threadIdx.x == 0) {
        double s8 = 0.0;
        #pragma unroll
        for (int i = 0; i < 8; i++) s8 += (double)ws[i];
        g_part[blockIdx.x] = s8;
    }
}

__global__ void finalize_loss_kernel(float* __restrict__ out_loss) {
    __shared__ double ws[256];
    double acc = 0.0;
    for (int i = threadIdx.x; i < 8192; i += 256) acc += g_part[i];
    ws[threadIdx.x] = acc;
    __syncthreads();
    for (int off = 128; off > 0; off >>= 1) {
        if (threadIdx.x < off) ws[threadIdx.x] += ws[threadIdx.x + off];
        __syncthreads();
    }
    if (threadIdx.x == 0) {
        double mse = ws[0] / (double)QUANT_ELEMS;
        out_loss[0] = (float)(1.25 * mse);
    }
}

// ---------------------------------------------------------------------------
extern "C" void kernel_launch(void* const* d_in, const int* in_sizes, int n_in,
                              void* d_out, int out_size) {
    const float* z  = (const float*)d_in[0];
    const float* cb = (const float*)d_in[1];
    float* out      = (float*)d_out;
    float* out_q    = out;
    float* out_idx  = out + QUANT_ELEMS;
    float* out_loss = out + QUANT_ELEMS + N_ROWS;

    cudaFuncSetAttribute(mma_kernel, cudaFuncAttributeMaxDynamicSharedMemorySize, SM_TOTAL);

    prep_cbnorm_kernel<<<K_CODES / 8, 256>>>(cb);
    prep_z_kernel<<<dim3(128, 8, 8), dim3(32, 8)>>>(z);
    row_norms_kernel<<<N_ROWS / 256, 256>>>(z);
    mma_kernel<<<dim3(N_ROWS / BM, K_CODES / BKN), 128, SM_TOTAL>>>();
    select_kernel<<<N_ROWS / 8, 256>>>(cb, out_idx);
    gather_loss_kernel<<<QUANT_ELEMS / 4 / 256, 256>>>(z, cb, out_q);
    finalize_loss_kernel<<<1, 256>>>(out_loss);
}

// round 8
// speedup vs baseline: 1.2999x; 1.2999x over previous
#include <cuda_runtime.h>
#include <cuda_bf16.h>
#include <cuda_fp16.h>
#include <cstdint>

// ---------------------------------------------------------------------------
// Problem constants
#define N_ROWS   32768          // B*H*W*L = 8*16*16*16
#define K_CODES  1024
#define D_DIM    256
#define S_SZ     4096
#define QUANT_ELEMS 8388608     // 8*256*4096

// GEMM tiling (Round-5 proven config): CTA 128x128, 8 warps, warp tile 32x64
#define BM 128
#define BKN 128
#define KC 64                   // bf16 k-chunk (128 bytes/row)

// smem layout (dynamic): A0 | B0 | A1 | B1 | bnorm
#define TILE_BYTES 16384        // 128 rows x 128B
#define SM_BNORM   65536
#define SM_TOTAL   66048

// ---------------------------------------------------------------------------
// Scratch (__device__ globals; no runtime allocation)
__device__ __nv_bfloat16 g_zbf[N_ROWS * D_DIM];      // z transposed (n,d) bf16
__device__ float  g_zt[N_ROWS * D_DIM];              // z transposed (n,d) fp32
__device__ __nv_bfloat16 g_cbbf[K_CODES * D_DIM];    // codebook bf16
__device__ __half g_scores_h[N_ROWS * K_CODES];      // approx scores fp16 (64 MB)
__device__ float  g_a[N_ROWS];                       // ||z_n||^2 (sequential-d fmaf!)
__device__ float  g_sabs[N_ROWS];                    // sum_d |z_nd|
__device__ float  g_b[K_CODES];                      // ||e_k||^2
__device__ int    g_idx[N_ROWS];                     // final indices
__device__ double g_part[8192];                      // loss partials

// ---------------------------------------------------------------------------
__device__ __forceinline__ uint32_t smem_u32(const void* p) {
    uint32_t a;
    asm("{ .reg .u64 t; cvta.to.shared.u64 t, %1; cvt.u32.u64 %0, t; }" : "=r"(a) : "l"(p));
    return a;
}
#define SW128(o) ((o) ^ (((o) >> 3) & 0x70))

__device__ __forceinline__ void cp16(uint32_t saddr, const void* gaddr) {
    asm volatile("cp.async.cg.shared.global [%0], [%1], 16;" :: "r"(saddr), "l"(gaddr));
}
#define CP_COMMIT() asm volatile("cp.async.commit_group;")
#define CP_WAIT(n)  asm volatile("cp.async.wait_group %0;" :: "n"(n))

__device__ __forceinline__ void ldsm_x4(uint32_t* r, uint32_t saddr) {
    asm volatile("ldmatrix.sync.aligned.m8n8.x4.shared.b16 {%0,%1,%2,%3}, [%4];"
                 : "=r"(r[0]), "=r"(r[1]), "=r"(r[2]), "=r"(r[3]) : "r"(saddr));
}
__device__ __forceinline__ void mma_bf16(float* c, const uint32_t* a, uint32_t b0, uint32_t b1) {
    asm volatile("mma.sync.aligned.m16n8k16.row.col.f32.bf16.bf16.f32 "
                 "{%0,%1,%2,%3}, {%4,%5,%6,%7}, {%8,%9}, {%0,%1,%2,%3};"
                 : "+f"(c[0]), "+f"(c[1]), "+f"(c[2]), "+f"(c[3])
                 : "r"(a[0]), "r"(a[1]), "r"(a[2]), "r"(a[3]), "r"(b0), "r"(b1));
}

__device__ __forceinline__ uint32_t pack_bf16x2(float lo, float hi) {
    __nv_bfloat162 t = __floats2bfloat162_rn(lo, hi);
    uint32_t u;
    memcpy(&u, &t, 4);
    return u;
}

// ---------------------------------------------------------------------------
// 1) Codebook: bf16 convert + ||e_k||^2, warp per row.
__global__ void prep_cbnorm_kernel(const float* __restrict__ cb) {
    int w = blockIdx.x * 8 + (threadIdx.x >> 5);
    int lane = threadIdx.x & 31;
    const float* p = cb + (size_t)w * D_DIM + lane * 8;
    float4 v0 = *(const float4*)p;
    float4 v1 = *(const float4*)(p + 4);
    uint4 packed;
    packed.x = pack_bf16x2(v0.x, v0.y);
    packed.y = pack_bf16x2(v0.z, v0.w);
    packed.z = pack_bf16x2(v1.x, v1.y);
    packed.w = pack_bf16x2(v1.z, v1.w);
    *(uint4*)(g_cbbf + (size_t)w * D_DIM + lane * 8) = packed;
    float acc = 0.0f;
    acc = fmaf(v0.x, v0.x, acc); acc = fmaf(v0.y, v0.y, acc);
    acc = fmaf(v0.z, v0.z, acc); acc = fmaf(v0.w, v0.w, acc);
    acc = fmaf(v1.x, v1.x, acc); acc = fmaf(v1.y, v1.y, acc);
    acc = fmaf(v1.z, v1.z, acc); acc = fmaf(v1.w, v1.w, acc);
    #pragma unroll
    for (int off = 16; off > 0; off >>= 1)
        acc += __shfl_xor_sync(0xffffffffu, acc, off);
    if (lane == 0) g_b[w] = acc;
}

// ---------------------------------------------------------------------------
// 2) Fused: transpose z -> (n,d) fp32 + bf16, AND per-row sequential norms.
//    Block: 256 threads, tile = 32 s-cols x 256 d (one batch b). One z read.
__global__ void __launch_bounds__(256)
prep_z_kernel(const float* __restrict__ z) {
    __shared__ float tile[32][257];                 // [s][d], bank(s+d)
    int x = threadIdx.x & 31, y = threadIdx.x >> 5; // lane, warp
    int s0 = blockIdx.x * 32;
    int b  = blockIdx.y;
    const float* zb = z + (size_t)b * (D_DIM * S_SZ) + s0;
    // load: warp y covers d = y + 8*i; lanes coalesced over s
    #pragma unroll 8
    for (int i = 0; i < 32; i++) {
        int d = y + 8 * i;
        tile[x][d] = zb[(size_t)d * S_SZ + x];
    }
    __syncthreads();
    // write transposed: warp y handles rows r = 4y..4y+3; lanes cover 32 d's
    #pragma unroll
    for (int rr = 0; rr < 4; rr++) {
        int r = y * 4 + rr;
        size_t n = (size_t)(b * S_SZ + s0 + r);
        #pragma unroll
        for (int c = 0; c < 8; c++) {
            int d = c * 32 + x;
            float v = tile[r][d];                   // bank (r + x) -> conflict-free
            g_zt[n * D_DIM + d]  = v;
            g_zbf[n * D_DIM + d] = __float2bfloat16(v);
        }
    }
    // sequential-d norms: thread t<32 owns row t (bit-exact fmaf chain order)
    if (threadIdx.x < 32) {
        int r = threadIdx.x;
        float acc = 0.0f, sab = 0.0f;
        #pragma unroll 8
        for (int d = 0; d < D_DIM; d++) {
            float v = tile[r][d];                   // bank (r + d) -> conflict-free
            acc = fmaf(v, v, acc);
            sab += fabsf(v);
        }
        int n = b * S_SZ + s0 + r;
        g_a[n] = acc;
        g_sabs[n] = sab;
    }
}

// ---------------------------------------------------------------------------
// 3) HMMA bf16 GEMM (Round-5 config): CTA 128x128, warp tile 32x64,
//    cp.async double buffered, SW128 smem. Epilogue: fp16 score stores ONLY.
__global__ void __launch_bounds__(256, 2)
mma_kernel() {
    extern __shared__ char smem[];
    uint32_t sb = smem_u32(smem);
    int tid  = threadIdx.x;
    int wid  = tid >> 5, lane = tid & 31;
    int wm   = wid & 3;              // 0..3  (32-row slice)
    int wn   = wid >> 2;             // 0..1  (64-col slice)
    int n0   = blockIdx.x * BM;
    int k0   = blockIdx.y * BKN;

    float* bsh = (float*)(smem + SM_BNORM);
    if (tid < BKN) bsh[tid] = g_b[k0 + tid];

    int lrow = tid >> 1;
    int lseg0 = (tid & 1) * 4;
    auto load_chunk = [&](int buf, int c) {
        uint32_t abase = sb + buf * 32768;
        uint32_t bbase = abase + TILE_BYTES;
        const __nv_bfloat16* ag = g_zbf  + (size_t)(n0 + lrow) * D_DIM + c * KC;
        const __nv_bfloat16* bg = g_cbbf + (size_t)(k0 + lrow) * D_DIM + c * KC;
        #pragma unroll
        for (int i = 0; i < 4; i++) {
            int seg = lseg0 + i;
            uint32_t soff = SW128(lrow * 128 + seg * 16);
            cp16(abase + soff, ag + seg * 8);
            cp16(bbase + soff, bg + seg * 8);
        }
    };

    float C[2][8][4];
    #pragma unroll
    for (int mf = 0; mf < 2; mf++)
        #pragma unroll
        for (int nf = 0; nf < 8; nf++)
            #pragma unroll
            for (int q = 0; q < 4; q++) C[mf][nf][q] = 0.0f;

    load_chunk(0, 0);
    CP_COMMIT();

    int lr = lane & 15;
    int lh = lane >> 4;

    for (int c = 0; c < 4; c++) {
        if (c < 3) { load_chunk((c + 1) & 1, c + 1); CP_COMMIT(); }
        if (c < 3) { CP_WAIT(1); } else { CP_WAIT(0); }
        __syncthreads();

        uint32_t abase = sb + (c & 1) * 32768;
        uint32_t bbase = abase + TILE_BYTES;

        #pragma unroll
        for (int ks = 0; ks < 4; ks++) {
            uint32_t a[2][4], bq[4][4];
            #pragma unroll
            for (int mf = 0; mf < 2; mf++) {
                int r = wm * 32 + mf * 16 + lr;
                ldsm_x4(a[mf], abase + SW128(r * 128 + (2 * ks + lh) * 16));
            }
            #pragma unroll
            for (int nf2 = 0; nf2 < 4; nf2++) {
                int r = wn * 64 + nf2 * 16 + lr;
                ldsm_x4(bq[nf2], bbase + SW128(r * 128 + (2 * ks + lh) * 16));
            }
            #pragma unroll
            for (int mf = 0; mf < 2; mf++)
                #pragma unroll
                for (int nf2 = 0; nf2 < 4; nf2++) {
                    mma_bf16(C[mf][2 * nf2],     a[mf], bq[nf2][0], bq[nf2][2]);
                    mma_bf16(C[mf][2 * nf2 + 1], a[mf], bq[nf2][1], bq[nf2][3]);
                }
        }
        __syncthreads();
    }

    // Epilogue: fp16 score stores only (argmin moved into select_kernel)
    int gq = lane >> 2;
    int qc = (lane & 3) * 2;
    #pragma unroll
    for (int mf = 0; mf < 2; mf++) {
        int r0 = n0 + wm * 32 + mf * 16 + gq;
        #pragma unroll
        for (int nf = 0; nf < 8; nf++) {
            int colL = wn * 64 + nf * 8 + qc;
            int kk = k0 + colL;
            float b0v = bsh[colL], b1v = bsh[colL + 1];
            float s00 = b0v - 2.0f * C[mf][nf][0];
            float s01 = b1v - 2.0f * C[mf][nf][1];
            float s10 = b0v - 2.0f * C[mf][nf][2];
            float s11 = b1v - 2.0f * C[mf][nf][3];
            *(__half2*)(g_scores_h + (size_t)r0 * K_CODES + kk) =
                __floats2half2_rn(s00, s01);
            *(__half2*)(g_scores_h + (size_t)(r0 + 8) * K_CODES + kk) =
                __floats2half2_rn(s10, s11);
        }
    }
}

// ---------------------------------------------------------------------------
// 4) Select: row-min (pass 1, contiguous loads) + candidate ballot + exact
//    fp32 rescore (pass 2, L1-hot). Warp per row.
__global__ void __launch_bounds__(256)
select_kernel(const float* __restrict__ cb, float* __restrict__ out_idx) {
    int w = threadIdx.x >> 5, lane = threadIdx.x & 31;
    int n = blockIdx.x * 8 + w;

    const float* zp = g_zt + (size_t)n * D_DIM + lane * 8;
    float4 z0 = *(const float4*)zp;
    float4 z1 = *(const float4*)(zp + 4);
    float a = g_a[n];

    const __half* sr = g_scores_h + (size_t)n * K_CODES;

    // Pass 1: row min of fp16 scores. Lane loads 32 contiguous halfs.
    float minv = 1e30f;
    {
        const uint4* sp = (const uint4*)(sr + lane * 32);
        #pragma unroll
        for (int q = 0; q < 4; q++) {
            uint4 u = sp[q];
            const __half2* h = (const __half2*)&u;
            #pragma unroll
            for (int e = 0; e < 4; e++) {
                float2 f = __half22float2(h[e]);
                minv = fminf(minv, fminf(f.x, f.y));
            }
        }
        #pragma unroll
        for (int off = 16; off > 0; off >>= 1)
            minv = fminf(minv, __shfl_xor_sync(0xffffffffu, minv, off));
    }
    // margin: 2x fp16 RN err (2.44e-4) + 2x bf16 GEMM err + exact-formula slack
    float thresh = minv + g_sabs[n] * 1.6e-5f + 7.0e-4f;

    // Pass 2: ballot candidates (L1-hot strided reads) + exact rescore.
    unsigned long long best = ~0ULL;
    #pragma unroll 4
    for (int j = 0; j < 32; j++) {
        float sv = __half2float(sr[lane + 32 * j]);
        unsigned mask = __ballot_sync(0xffffffffu, sv <= thresh);
        while (mask) {
            int src = __ffs(mask) - 1;
            mask &= mask - 1;
            int kc = 32 * j + src;
            const float* e = cb + (size_t)kc * D_DIM + lane * 8;
            float4 e0 = *(const float4*)e;
            float4 e1 = *(const float4*)(e + 4);
            float acc = 0.0f;
            acc = fmaf(z0.x, e0.x, acc); acc = fmaf(z0.y, e0.y, acc);
            acc = fmaf(z0.z, e0.z, acc); acc = fmaf(z0.w, e0.w, acc);
            acc = fmaf(z1.x, e1.x, acc); acc = fmaf(z1.y, e1.y, acc);
            acc = fmaf(z1.z, e1.z, acc); acc = fmaf(z1.w, e1.w, acc);
            #pragma unroll
            for (int off = 16; off > 0; off >>= 1)
                acc += __shfl_xor_sync(0xffffffffu, acc, off);
            float tsum = a + g_b[kc];                // fl(a + b)
            float dv = tsum - 2.0f * acc;            // fl(t - 2c)
            unsigned long long p =
                ((unsigned long long)__float_as_uint(dv) << 32) | (unsigned)kc;
            best = min(best, p);
        }
    }
    if (lane == 0) {
        int kk = (int)(unsigned)(best & 0xFFFFFFFFULL);
        g_idx[n] = kk;
        out_idx[n] = (float)kk;
    }
}

// ---------------------------------------------------------------------------
// 5) Gather + straight-through + loss partials
__global__ void gather_loss_kernel(const float* __restrict__ z,
                                   const float* __restrict__ cb,
                                   float* __restrict__ out_q) {
    int gid4 = blockIdx.x * blockDim.x + threadIdx.x;
    int base = gid4 * 4;
    int s = base & 4095;
    int r = base >> 12;
    int d = r & 255;
    int b = r >> 8;
    int n = b * S_SZ + s;
    float4 zv = *(const float4*)(z + base);
    float4 ov;
    int k0 = g_idx[n], k1 = g_idx[n + 1], k2 = g_idx[n + 2], k3 = g_idx[n + 3];
    float q0 = cb[(size_t)k0 * D_DIM + d];
    float q1 = cb[(size_t)k1 * D_DIM + d];
    float q2 = cb[(size_t)k2 * D_DIM + d];
    float q3 = cb[(size_t)k3 * D_DIM + d];
    float d0 = q0 - zv.x, d1 = q1 - zv.y, d2 = q2 - zv.z, d3 = q3 - zv.w;
    ov.x = zv.x + d0; ov.y = zv.y + d1; ov.z = zv.z + d2; ov.w = zv.w + d3;
    *(float4*)(out_q + base) = ov;
    float part = fmaf(d0, d0, fmaf(d1, d1, fmaf(d2, d2, d3 * d3)));
    #pragma unroll
    for (int off = 16; off > 0; off >>= 1)
        part += __shfl_down_sync(0xffffffffu, part, off);
    __shared__ float ws[8];
    int lane = threadIdx.x & 31, w = threadIdx.x >> 5;
    if (lane == 0) ws[w] = part;
    __syncthreads();
    if (threadIdx.x == 0) {
        double s8 = 0.0;
        #pragma unroll
        for (int i = 0; i < 8; i++) s8 += (double)ws[i];
        g_part[blockIdx.x] = s8;
    }
}

__global__ void finalize_loss_kernel(float* __restrict__ out_loss) {
    __shared__ double ws[256];
    double acc = 0.0;
    for (int i = threadIdx.x; i < 8192; i += 256) acc += g_part[i];
    ws[threadIdx.x] = acc;
    __syncthreads();
    for (int off = 128; off > 0; off >>= 1) {
        if (threadIdx.x < off) ws[threadIdx.x] += ws[threadIdx.x + off];
        __syncthreads();
    }
    if (threadIdx.x == 0) {
        double mse = ws[0] / (double)QUANT_ELEMS;
        out_loss[0] = (float)(1.25 * mse);
    }
}

// ---------------------------------------------------------------------------
extern "C" void kernel_launch(void* const* d_in, const int* in_sizes, int n_in,
                              void* d_out, int out_size) {
    const float* z  = (const float*)d_in[0];
    const float* cb = (const float*)d_in[1];
    float* out      = (float*)d_out;
    float* out_q    = out;
    float* out_idx  = out + QUANT_ELEMS;
    float* out_loss = out + QUANT_ELEMS + N_ROWS;

    cudaFuncSetAttribute(mma_kernel, cudaFuncAttributeMaxDynamicSharedMemorySize, SM_TOTAL);

    prep_cbnorm_kernel<<<K_CODES / 8, 256>>>(cb);
    prep_z_kernel<<<dim3(S_SZ / 32, 8), 256>>>(z);
    mma_kernel<<<dim3(N_ROWS / BM, K_CODES / BKN), 256, SM_TOTAL>>>();
    select_kernel<<<N_ROWS / 8, 256>>>(cb, out_idx);
    gather_loss_kernel<<<QUANT_ELEMS / 4 / 256, 256>>>(z, cb, out_q);
    finalize_loss_kernel<<<1, 256>>>(out_loss);
}